// round 7
// baseline (speedup 1.0000x reference)
#include <cuda_runtime.h>

// ---------------------------------------------------------------------------
// HydraAttention: qkv = x@Wqkv+b; q,k cosine-normalized over D; kv = sum_T k*v;
// out = (q * kv) @ Wout + bout.   B=4, T=4096, D=1024.
// Baseline fp32 SIMT implementation:
//   k1: SGEMM 16384x3072x1024  -> g_qkv
//   k2: per-row inv-norms of q,k
//   k3: two-stage deterministic pool kv[b,d] = sum_t khat*v
//   k4: SGEMM 16384x1024x1024 with A-load fused scaling q*invq*kv
// ---------------------------------------------------------------------------

#define BATCH 4
#define SEQT  4096
#define DMODEL 1024
#define MROWS (BATCH * SEQT)          // 16384
#define N3D   (3 * DMODEL)            // 3072
#define TCHUNKS 32                    // T split for the pool reduction
#define TPER    (SEQT / TCHUNKS)      // 128

// Scratch (device globals — allocation-free per harness rules)
__device__ float g_qkv[(size_t)MROWS * N3D];     // ~192 MB
__device__ float g_invq[MROWS];
__device__ float g_invk[MROWS];
__device__ float g_kvpart[TCHUNKS * BATCH * DMODEL];
__device__ float g_kv[BATCH * DMODEL];

// ---------------------------------------------------------------------------
// Tiled SGEMM: C[M,N] = A[M,K] @ B[K,N] + bias[N]
// Tile 128x128x8, 256 threads, 8x8 accumulators per thread.
// FUSED: A element (m,k) is scaled by invq[m] * kvp[batch(m)*D + k]
//        (implements hid = q_hat * kv without materializing it).
// ---------------------------------------------------------------------------
template <bool FUSED>
__global__ __launch_bounds__(256, 2)
void sgemm_kernel(const float* __restrict__ A, int lda,
                  const float* __restrict__ B, int ldb,
                  const float* __restrict__ bias,
                  float* __restrict__ C, int ldc,
                  int K,
                  const float* __restrict__ invq,
                  const float* __restrict__ kvp)
{
    __shared__ float As[8][128];
    __shared__ float Bs[8][128];

    const int tid = threadIdx.x;
    const int m0  = blockIdx.y * 128;
    const int n0  = blockIdx.x * 128;

    // A tile loader: 128 rows x 8 cols, one float4 per thread
    const int arow = tid >> 1;             // 0..127
    const int acol = (tid & 1) << 2;       // 0 or 4
    // B tile loader: 8 rows x 128 cols, one float4 per thread
    const int brow = tid >> 5;             // 0..7
    const int bcol = (tid & 31) << 2;      // 0..124

    const int tx = tid & 15;
    const int ty = tid >> 4;

    float acc[8][8];
    #pragma unroll
    for (int i = 0; i < 8; ++i)
        #pragma unroll
        for (int j = 0; j < 8; ++j) acc[i][j] = 0.f;

    const float* Aptr = A + (size_t)(m0 + arow) * lda + acol;
    const float* Bptr = B + (size_t)brow * ldb + n0 + bcol;

    float invq_r = 0.f;
    int   kvbase = 0;
    if (FUSED) {
        invq_r = invq[m0 + arow];
        kvbase = ((m0 + arow) >> 12) << 10;   // batch(m) * DMODEL (T=4096)
    }

    for (int k0 = 0; k0 < K; k0 += 8) {
        float4 av = *reinterpret_cast<const float4*>(Aptr + k0);
        float4 bv = *reinterpret_cast<const float4*>(Bptr + (size_t)k0 * ldb);
        if (FUSED) {
            const int kc = kvbase + k0 + acol;
            av.x *= invq_r * kvp[kc + 0];
            av.y *= invq_r * kvp[kc + 1];
            av.z *= invq_r * kvp[kc + 2];
            av.w *= invq_r * kvp[kc + 3];
        }
        __syncthreads();
        As[acol + 0][arow] = av.x;
        As[acol + 1][arow] = av.y;
        As[acol + 2][arow] = av.z;
        As[acol + 3][arow] = av.w;
        *reinterpret_cast<float4*>(&Bs[brow][bcol]) = bv;
        __syncthreads();

        #pragma unroll
        for (int kk = 0; kk < 8; ++kk) {
            float4 a0 = *reinterpret_cast<const float4*>(&As[kk][ty * 8]);
            float4 a1 = *reinterpret_cast<const float4*>(&As[kk][ty * 8 + 4]);
            float4 b0 = *reinterpret_cast<const float4*>(&Bs[kk][tx * 8]);
            float4 b1 = *reinterpret_cast<const float4*>(&Bs[kk][tx * 8 + 4]);
            float a[8] = {a0.x, a0.y, a0.z, a0.w, a1.x, a1.y, a1.z, a1.w};
            float b[8] = {b0.x, b0.y, b0.z, b0.w, b1.x, b1.y, b1.z, b1.w};
            #pragma unroll
            for (int i = 0; i < 8; ++i)
                #pragma unroll
                for (int j = 0; j < 8; ++j)
                    acc[i][j] += a[i] * b[j];
        }
    }

    // Epilogue: add bias, vectorized store
    float4 bia0 = *reinterpret_cast<const float4*>(bias + n0 + tx * 8);
    float4 bia1 = *reinterpret_cast<const float4*>(bias + n0 + tx * 8 + 4);
    #pragma unroll
    for (int i = 0; i < 8; ++i) {
        float* crow = C + (size_t)(m0 + ty * 8 + i) * ldc + n0 + tx * 8;
        float4 v0, v1;
        v0.x = acc[i][0] + bia0.x; v0.y = acc[i][1] + bia0.y;
        v0.z = acc[i][2] + bia0.z; v0.w = acc[i][3] + bia0.w;
        v1.x = acc[i][4] + bia1.x; v1.y = acc[i][5] + bia1.y;
        v1.z = acc[i][6] + bia1.z; v1.w = acc[i][7] + bia1.w;
        *reinterpret_cast<float4*>(crow)     = v0;
        *reinterpret_cast<float4*>(crow + 4) = v1;
    }
}

// ---------------------------------------------------------------------------
// Per-row inverse L2 norms of q (cols 0..1023) and k (cols 1024..2047)
// ---------------------------------------------------------------------------
__global__ void rownorm_kernel()
{
    __shared__ float sqs[8], sks[8];
    const int r = blockIdx.x;
    const float* base = g_qkv + (size_t)r * N3D;

    float sq = 0.f, sk = 0.f;
    for (int d = threadIdx.x; d < DMODEL; d += 256) {
        float qv = base[d];
        float kv = base[DMODEL + d];
        sq += qv * qv;
        sk += kv * kv;
    }
    #pragma unroll
    for (int o = 16; o > 0; o >>= 1) {
        sq += __shfl_down_sync(0xffffffffu, sq, o);
        sk += __shfl_down_sync(0xffffffffu, sk, o);
    }
    const int w = threadIdx.x >> 5, l = threadIdx.x & 31;
    if (l == 0) { sqs[w] = sq; sks[w] = sk; }
    __syncthreads();
    if (threadIdx.x == 0) {
        float a = 0.f, b = 0.f;
        #pragma unroll
        for (int i = 0; i < 8; ++i) { a += sqs[i]; b += sks[i]; }
        g_invq[r] = rsqrtf(a);
        g_invk[r] = rsqrtf(b);
    }
}

// ---------------------------------------------------------------------------
// Pool stage 1: per-(T-chunk) partial kv[b,d] = sum_{t in chunk} khat * v
// grid (BATCH*DMODEL/256, TCHUNKS) — deterministic (no atomics)
// ---------------------------------------------------------------------------
__global__ void kvpool_partial_kernel()
{
    const int gi = blockIdx.x * 256 + threadIdx.x;   // 0..4095
    const int b  = gi >> 10;
    const int d  = gi & (DMODEL - 1);
    const int t0 = blockIdx.y * TPER;

    const int row0 = b * SEQT + t0;
    const float* p = g_qkv + (size_t)row0 * N3D + d;

    float acc = 0.f;
    #pragma unroll 4
    for (int t = 0; t < TPER; ++t) {
        float ik = g_invk[row0 + t];
        acc += (p[DMODEL] * ik) * p[2 * DMODEL];
        p += N3D;
    }
    g_kvpart[blockIdx.y * (BATCH * DMODEL) + gi] = acc;
}

// Pool stage 2: reduce the TCHUNKS partials
__global__ void kvpool_reduce_kernel()
{
    const int gi = blockIdx.x * 256 + threadIdx.x;
    float s = 0.f;
    #pragma unroll
    for (int c = 0; c < TCHUNKS; ++c)
        s += g_kvpart[c * (BATCH * DMODEL) + gi];
    g_kv[gi] = s;
}

// ---------------------------------------------------------------------------
// Launch
// ---------------------------------------------------------------------------
extern "C" void kernel_launch(void* const* d_in, const int* in_sizes, int n_in,
                              void* d_out, int out_size)
{
    const float* x    = (const float*)d_in[0];
    const float* Wqkv = (const float*)d_in[1];
    const float* bqkv = (const float*)d_in[2];
    const float* Wout = (const float*)d_in[3];
    const float* bout = (const float*)d_in[4];
    float* out = (float*)d_out;

    float *qkv, *invq, *kv;
    cudaGetSymbolAddress((void**)&qkv,  g_qkv);
    cudaGetSymbolAddress((void**)&invq, g_invq);
    cudaGetSymbolAddress((void**)&kv,   g_kv);

    // GEMM1: qkv = x @ Wqkv + bqkv
    sgemm_kernel<false><<<dim3(N3D / 128, MROWS / 128), 256>>>(
        x, DMODEL, Wqkv, N3D, bqkv, qkv, N3D, DMODEL, nullptr, nullptr);

    // Row inverse norms for q and k
    rownorm_kernel<<<MROWS, 256>>>();

    // kv pool (deterministic 2-stage)
    kvpool_partial_kernel<<<dim3(BATCH * DMODEL / 256, TCHUNKS), 256>>>();
    kvpool_reduce_kernel<<<BATCH * DMODEL / 256, 256>>>();

    // GEMM2: out = (qhat * kv) @ Wout + bout  (scaling fused into A load)
    sgemm_kernel<true><<<dim3(DMODEL / 128, MROWS / 128), 256>>>(
        qkv, N3D, Wout, DMODEL, bout, out, DMODEL, DMODEL, invq, kv);
}

// round 8
// speedup vs baseline: 3.1472x; 3.1472x over previous
#include <cuda_runtime.h>
#include <cstdint>

// ---------------------------------------------------------------------------
// HydraAttention, TF32 tensor-core version.
//   prep : RN-round x, Wqkv, Wout to tf32 precision (removes truncation bias)
//   k1   : TF32 GEMM 16384x3072x1024 -> g_qkv (+bias, fp32 accum)
//   k2   : per-row inv L2 norms of q,k
//   k3   : deterministic 2-stage pool kv[b,d] = sum_t khat*v
//   k4   : A2 = rn_tf32(q * invq * kv)    (fused scale + round)
//   k5   : TF32 GEMM 16384x1024x1024 -> out (+bias)
// GEMM: mma.sync.m16n8k8.tf32, CTA 128x256x32, warp 64x64, cp.async 3-stage.
// ---------------------------------------------------------------------------

#define BATCH 4
#define SEQT  4096
#define DMODEL 1024
#define MROWS (BATCH * SEQT)          // 16384
#define N3D   (3 * DMODEL)            // 3072
#define TCHUNKS 32
#define TPER    (SEQT / TCHUNKS)      // 128

// GEMM tiling
#define BM 128
#define BN 256
#define BK 32
#define KITERS (DMODEL / BK)          // 32
#define AS_LD 36                      // A smem row pitch (floats): banks (4m+k)%32
#define BS_LD 264                     // B smem row pitch (floats): banks (8k+n)%32
#define AS_SZ (BM * AS_LD)            // 4608 floats / stage
#define BS_SZ (BK * BS_LD)            // 8448 floats / stage
#define STG_STRIDE (AS_SZ + BS_SZ)    // 13056 floats
#define SMEM_BYTES (3 * STG_STRIDE * 4)   // 156672 B

// Scratch (device globals — allocation-free per harness rules)
__device__ float g_qkv[(size_t)MROWS * N3D];      // 192 MB
__device__ float g_xr[(size_t)MROWS * DMODEL];    // 64 MB (tf32-rounded x)
__device__ float g_a2[(size_t)MROWS * DMODEL];    // 64 MB (rounded q*invq*kv)
__device__ float g_wqkvr[(size_t)DMODEL * N3D];   // 12 MB
__device__ float g_woutr[(size_t)DMODEL * DMODEL];// 4 MB
__device__ float g_invq[MROWS];
__device__ float g_invk[MROWS];
__device__ float g_kvpart[TCHUNKS * BATCH * DMODEL];
__device__ float g_kv[BATCH * DMODEL];

// ---------------------------------------------------------------------------
// helpers
// ---------------------------------------------------------------------------
__device__ __forceinline__ float rn_tf32(float f) {
    uint32_t u; asm("cvt.rna.tf32.f32 %0, %1;" : "=r"(u) : "f"(f));
    return __uint_as_float(u);
}

__device__ __forceinline__ void cp16(uint32_t s, const void* g) {
    asm volatile("cp.async.cg.shared.global [%0], [%1], 16;" :: "r"(s), "l"(g));
}
__device__ __forceinline__ void cp_commit() { asm volatile("cp.async.commit_group;"); }
__device__ __forceinline__ void cp_wait1()  { asm volatile("cp.async.wait_group 1;"); }

__device__ __forceinline__ void mma_tf32(float* c, const uint32_t* a, const uint32_t* b) {
    asm volatile(
        "mma.sync.aligned.m16n8k8.row.col.f32.tf32.tf32.f32 "
        "{%0,%1,%2,%3}, {%4,%5,%6,%7}, {%8,%9}, {%0,%1,%2,%3};"
        : "+f"(c[0]), "+f"(c[1]), "+f"(c[2]), "+f"(c[3])
        : "r"(a[0]), "r"(a[1]), "r"(a[2]), "r"(a[3]), "r"(b[0]), "r"(b[1]));
}

// Stage fill: A tile 128x32 (row-major, native), B tile 32x256 (row-major).
__device__ __forceinline__ void stage_issue(
    uint32_t smu, int stg, int tid,
    const float* __restrict__ A, int lda,
    const float* __restrict__ B, int ldb,
    int m0, int n0, int k0)
{
    uint32_t sa = smu + (uint32_t)(stg * STG_STRIDE) * 4u;
    uint32_t sb = sa + (uint32_t)AS_SZ * 4u;
    const float* Ab = A + (size_t)m0 * lda + k0;
    #pragma unroll
    for (int j = 0; j < 4; ++j) {                 // 128x32 = 1024 chunks of 16B
        int c = tid + j * 256;
        int r = c >> 3, col = (c & 7) << 2;
        cp16(sa + (uint32_t)(r * AS_LD + col) * 4u, Ab + (size_t)r * lda + col);
    }
    const float* Bb = B + (size_t)k0 * ldb + n0;
    #pragma unroll
    for (int j = 0; j < 8; ++j) {                 // 32x256 = 2048 chunks
        int c = tid + j * 256;
        int r = c >> 6, col = (c & 63) << 2;
        cp16(sb + (uint32_t)(r * BS_LD + col) * 4u, Bb + (size_t)r * ldb + col);
    }
}

// ---------------------------------------------------------------------------
// TF32 GEMM: C[M,N] = A[M,K] @ B[K,N] + bias[N]   (fp32 accumulate)
// Operands must already be tf32-rounded fp32 values.
// ---------------------------------------------------------------------------
__global__ __launch_bounds__(256, 1)
void gemm_tf32_kernel(const float* __restrict__ A, int lda,
                      const float* __restrict__ B, int ldb,
                      const float* __restrict__ bias,
                      float* __restrict__ C, int ldc)
{
    extern __shared__ float sm[];
    uint32_t smu = (uint32_t)__cvta_generic_to_shared(sm);
    const int tid = threadIdx.x;
    const int m0  = blockIdx.y * BM;
    const int n0  = blockIdx.x * BN;
    const int w   = tid >> 5, l = tid & 31;
    const int wm  = w & 1;            // 0..1  (M)
    const int wn  = w >> 1;           // 0..3  (N)
    const int gid = l >> 2, tig = l & 3;

    float acc[4][8][4];
    #pragma unroll
    for (int i = 0; i < 4; ++i)
        #pragma unroll
        for (int j = 0; j < 8; ++j)
            #pragma unroll
            for (int q = 0; q < 4; ++q) acc[i][j][q] = 0.f;

    stage_issue(smu, 0, tid, A, lda, B, ldb, m0, n0, 0);  cp_commit();
    stage_issue(smu, 1, tid, A, lda, B, ldb, m0, n0, BK); cp_commit();

    for (int it = 0; it < KITERS; ++it) {
        cp_wait1();
        __syncthreads();
        if (it + 2 < KITERS)
            stage_issue(smu, (it + 2) % 3, tid, A, lda, B, ldb, m0, n0, (it + 2) * BK);
        cp_commit();

        const float* As = sm + (it % 3) * STG_STRIDE;
        const float* Bs = As + AS_SZ;

        #pragma unroll
        for (int ks = 0; ks < BK; ks += 8) {
            uint32_t af[4][4], bf[8][2];
            #pragma unroll
            for (int i = 0; i < 4; ++i) {
                const float* ap = As + (wm * 64 + i * 16 + gid) * AS_LD + ks + tig;
                af[i][0] = __float_as_uint(ap[0]);
                af[i][1] = __float_as_uint(ap[8 * AS_LD]);
                af[i][2] = __float_as_uint(ap[4]);
                af[i][3] = __float_as_uint(ap[8 * AS_LD + 4]);
            }
            #pragma unroll
            for (int j = 0; j < 8; ++j) {
                const float* bp = Bs + (ks + tig) * BS_LD + wn * 64 + j * 8 + gid;
                bf[j][0] = __float_as_uint(bp[0]);
                bf[j][1] = __float_as_uint(bp[4 * BS_LD]);
            }
            #pragma unroll
            for (int i = 0; i < 4; ++i)
                #pragma unroll
                for (int j = 0; j < 8; ++j)
                    mma_tf32(acc[i][j], af[i], bf[j]);
        }
    }

    // Epilogue: bias + store (float2 per c-pair)
    #pragma unroll
    for (int i = 0; i < 4; ++i) {
        int r0 = m0 + wm * 64 + i * 16 + gid;
        #pragma unroll
        for (int j = 0; j < 8; ++j) {
            int col = n0 + wn * 64 + j * 8 + 2 * tig;
            float b0 = bias[col], b1 = bias[col + 1];
            float2 v0 = make_float2(acc[i][j][0] + b0, acc[i][j][1] + b1);
            float2 v1 = make_float2(acc[i][j][2] + b0, acc[i][j][3] + b1);
            *(float2*)&C[(size_t)r0 * ldc + col]       = v0;
            *(float2*)&C[(size_t)(r0 + 8) * ldc + col] = v1;
        }
    }
}

// ---------------------------------------------------------------------------
// Elementwise RN-round to tf32 precision
// ---------------------------------------------------------------------------
__global__ void round_tf32_kernel(const float* __restrict__ in,
                                  float* __restrict__ out, int n4)
{
    int i = blockIdx.x * 256 + threadIdx.x;
    if (i >= n4) return;
    float4 v = ((const float4*)in)[i];
    v.x = rn_tf32(v.x); v.y = rn_tf32(v.y);
    v.z = rn_tf32(v.z); v.w = rn_tf32(v.w);
    ((float4*)out)[i] = v;
}

// A2[m][k] = rn_tf32( q[m,k] * invq[m] * kv[batch(m), k] )
__global__ void scale_round_kernel()
{
    int i   = blockIdx.x * 256 + threadIdx.x;     // float4 index
    int row = i >> 8;
    int c   = (i & 255) << 2;
    float iq = g_invq[row];
    float4 q  = *(const float4*)(g_qkv + (size_t)row * N3D + c);
    float4 kv = *(const float4*)(g_kv + ((row >> 12) << 10) + c);
    float4 o;
    o.x = rn_tf32(q.x * iq * kv.x);
    o.y = rn_tf32(q.y * iq * kv.y);
    o.z = rn_tf32(q.z * iq * kv.z);
    o.w = rn_tf32(q.w * iq * kv.w);
    ((float4*)g_a2)[i] = o;
}

// ---------------------------------------------------------------------------
// Per-row inverse L2 norms of q (cols 0..1023) and k (cols 1024..2047)
// ---------------------------------------------------------------------------
__global__ void rownorm_kernel()
{
    __shared__ float sqs[8], sks[8];
    const int r = blockIdx.x;
    const float* base = g_qkv + (size_t)r * N3D;

    float sq = 0.f, sk = 0.f;
    for (int d = threadIdx.x; d < DMODEL; d += 256) {
        float qv = base[d];
        float kv = base[DMODEL + d];
        sq += qv * qv;
        sk += kv * kv;
    }
    #pragma unroll
    for (int o = 16; o > 0; o >>= 1) {
        sq += __shfl_down_sync(0xffffffffu, sq, o);
        sk += __shfl_down_sync(0xffffffffu, sk, o);
    }
    const int w = threadIdx.x >> 5, l = threadIdx.x & 31;
    if (l == 0) { sqs[w] = sq; sks[w] = sk; }
    __syncthreads();
    if (threadIdx.x == 0) {
        float a = 0.f, b = 0.f;
        #pragma unroll
        for (int i = 0; i < 8; ++i) { a += sqs[i]; b += sks[i]; }
        g_invq[r] = rsqrtf(a);
        g_invk[r] = rsqrtf(b);
    }
}

// ---------------------------------------------------------------------------
// Pool stage 1 + 2 (deterministic, no atomics)
// ---------------------------------------------------------------------------
__global__ void kvpool_partial_kernel()
{
    const int gi = blockIdx.x * 256 + threadIdx.x;   // 0..4095
    const int b  = gi >> 10;
    const int d  = gi & (DMODEL - 1);
    const int t0 = blockIdx.y * TPER;

    const int row0 = b * SEQT + t0;
    const float* p = g_qkv + (size_t)row0 * N3D + d;

    float acc = 0.f;
    #pragma unroll 4
    for (int t = 0; t < TPER; ++t) {
        float ik = g_invk[row0 + t];
        acc += (p[DMODEL] * ik) * p[2 * DMODEL];
        p += N3D;
    }
    g_kvpart[blockIdx.y * (BATCH * DMODEL) + gi] = acc;
}

__global__ void kvpool_reduce_kernel()
{
    const int gi = blockIdx.x * 256 + threadIdx.x;
    float s = 0.f;
    #pragma unroll
    for (int c = 0; c < TCHUNKS; ++c)
        s += g_kvpart[c * (BATCH * DMODEL) + gi];
    g_kv[gi] = s;
}

// ---------------------------------------------------------------------------
// Launch
// ---------------------------------------------------------------------------
extern "C" void kernel_launch(void* const* d_in, const int* in_sizes, int n_in,
                              void* d_out, int out_size)
{
    const float* x    = (const float*)d_in[0];
    const float* Wqkv = (const float*)d_in[1];
    const float* bqkv = (const float*)d_in[2];
    const float* Wout = (const float*)d_in[3];
    const float* bout = (const float*)d_in[4];
    float* out = (float*)d_out;

    float *qkv, *xr, *a2, *wqkvr, *woutr;
    cudaGetSymbolAddress((void**)&qkv,   g_qkv);
    cudaGetSymbolAddress((void**)&xr,    g_xr);
    cudaGetSymbolAddress((void**)&a2,    g_a2);
    cudaGetSymbolAddress((void**)&wqkvr, g_wqkvr);
    cudaGetSymbolAddress((void**)&woutr, g_woutr);

    cudaFuncSetAttribute(gemm_tf32_kernel,
                         cudaFuncAttributeMaxDynamicSharedMemorySize, SMEM_BYTES);

    // RN-round operands to tf32 precision (kills truncation bias)
    round_tf32_kernel<<<(MROWS * DMODEL / 4) / 256, 256>>>(x, xr, MROWS * DMODEL / 4);
    round_tf32_kernel<<<(DMODEL * N3D / 4) / 256, 256>>>(Wqkv, wqkvr, DMODEL * N3D / 4);
    round_tf32_kernel<<<(DMODEL * DMODEL / 4) / 256, 256>>>(Wout, woutr, DMODEL * DMODEL / 4);

    // GEMM1: qkv = xr @ Wqkvr + bqkv
    gemm_tf32_kernel<<<dim3(N3D / BN, MROWS / BM), 256, SMEM_BYTES>>>(
        xr, DMODEL, wqkvr, N3D, bqkv, qkv, N3D);

    rownorm_kernel<<<MROWS, 256>>>();
    kvpool_partial_kernel<<<dim3(BATCH * DMODEL / 256, TCHUNKS), 256>>>();
    kvpool_reduce_kernel<<<BATCH * DMODEL / 256, 256>>>();

    // A2 = rn_tf32(q * invq * kv)
    scale_round_kernel<<<MROWS, 256>>>();

    // GEMM2: out = A2 @ Woutr + bout
    gemm_tf32_kernel<<<dim3(DMODEL / BN, MROWS / BM), 256, SMEM_BYTES>>>(
        a2, DMODEL, woutr, DMODEL, bout, out, DMODEL);
}